// round 2
// baseline (speedup 1.0000x reference)
#include <cuda_runtime.h>
#include <cuda_bf16.h>
#include <math.h>
#include <stdint.h>

#define EPSF  1e-5f
#define MAXN  0.99999f
#define NQ    2048
#define HID   1024
#define DD    256
#define MM    65536
#define KNN   16
#define NSLICE 16
#define MSL   (MM / NSLICE)
#define QB    64
#define MT    128
#define KCH   32
#define FINF  3.402823466e38f

#define QSTR 264   // q smem row stride (bf16 elems)
#define MSTR 72    // m smem row stride (bf16 elems)
#define KSTR 129   // key smem row stride (f32 elems)

// ---------------- device scratch (no cudaMalloc allowed) ----------------
__device__ float g_tmp1[NQ * DD];
__device__ float g_G[NQ * DD];
__device__ float g_tmp2[NQ * DD];
__device__ float g_x2[NQ];
__device__ float g_omx2[NQ];
__device__ __nv_bfloat16 g_qhi[NQ * DD];
__device__ __nv_bfloat16 g_qlo[NQ * DD];
__device__ float g_mb[(size_t)MM * DD];             // 64 MB projected memory bank (fp32, for gather)
__device__ __nv_bfloat16 g_mhi[(size_t)MM * DD];    // 32 MB
__device__ __nv_bfloat16 g_mlo[(size_t)MM * DD];    // 32 MB
__device__ float g_y2[MM];
__device__ float g_omy2[MM];
__device__ float g_pkey[NQ * NSLICE * KNN];
__device__ int   g_pidx[NQ * NSLICE * KNN];
__device__ float g_ret[NQ * DD];
__device__ float g_tmp3[NQ * HID];

// ---------------- helpers ----------------
__device__ __forceinline__ float blockReduceSum256(float v) {
    __shared__ float sred[8];
    #pragma unroll
    for (int o = 16; o > 0; o >>= 1) v += __shfl_down_sync(0xffffffffu, v, o);
    int w = threadIdx.x >> 5;
    if ((threadIdx.x & 31) == 0) sred[w] = v;
    __syncthreads();
    if (threadIdx.x < 32) {
        float r = (threadIdx.x < 8) ? sred[threadIdx.x] : 0.0f;
        #pragma unroll
        for (int o = 4; o > 0; o >>= 1) r += __shfl_down_sync(0xffffffffu, r, o);
        if (threadIdx.x == 0) sred[0] = r;
    }
    __syncthreads();
    float r = sred[0];
    __syncthreads();
    return r;
}

__device__ __forceinline__ uint32_t s2u(const void* p) {
    return (uint32_t)__cvta_generic_to_shared(p);
}

__device__ __forceinline__ void ldsm4(uint32_t& r0, uint32_t& r1, uint32_t& r2, uint32_t& r3, uint32_t addr) {
    asm volatile("ldmatrix.sync.aligned.m8n8.x4.shared.b16 {%0,%1,%2,%3}, [%4];"
                 : "=r"(r0), "=r"(r1), "=r"(r2), "=r"(r3) : "r"(addr));
}

__device__ __forceinline__ void mma_bf16(float (&d)[4], const uint32_t (&a)[4], uint32_t b0, uint32_t b1) {
    asm volatile("mma.sync.aligned.m16n8k16.row.col.f32.bf16.bf16.f32 "
                 "{%0,%1,%2,%3}, {%4,%5,%6,%7}, {%8,%9}, {%0,%1,%2,%3};"
                 : "+f"(d[0]), "+f"(d[1]), "+f"(d[2]), "+f"(d[3])
                 : "r"(a[0]), "r"(a[1]), "r"(a[2]), "r"(a[3]), "r"(b0), "r"(b1));
}

// ---------------- generic 64x64 tiled fp32 GEMM: C = A[MxK] @ B[KxN] ----------------
__global__ void __launch_bounds__(256) gemm64x64(
    const float* __restrict__ A, const float* __restrict__ B,
    float* __restrict__ C, int M, int N, int Kd)
{
    __shared__ float As[KCH * 68];
    __shared__ float Bs[KCH * 68];
    int tid = threadIdx.x;
    int tx = tid & 15, ty = tid >> 4;
    int m0 = blockIdx.x * 64, n0 = blockIdx.y * 64;
    float acc[4][4] = {};
    for (int k0 = 0; k0 < Kd; k0 += KCH) {
        for (int i = tid; i < 64 * KCH; i += 256) {
            int m = i >> 5, k = i & 31;
            As[k * 68 + m] = A[(size_t)(m0 + m) * Kd + k0 + k];
        }
        for (int i = tid; i < KCH * 64; i += 256) {
            int k = i >> 6, n = i & 63;
            Bs[k * 68 + n] = B[(size_t)(k0 + k) * N + n0 + n];
        }
        __syncthreads();
        #pragma unroll
        for (int k = 0; k < KCH; k++) {
            float4 bv = *(const float4*)&Bs[k * 68 + tx * 4];
            float4 av = *(const float4*)&As[k * 68 + ty * 4];
            acc[0][0] += av.x * bv.x; acc[0][1] += av.x * bv.y; acc[0][2] += av.x * bv.z; acc[0][3] += av.x * bv.w;
            acc[1][0] += av.y * bv.x; acc[1][1] += av.y * bv.y; acc[1][2] += av.y * bv.z; acc[1][3] += av.y * bv.w;
            acc[2][0] += av.z * bv.x; acc[2][1] += av.z * bv.y; acc[2][2] += av.z * bv.z; acc[2][3] += av.z * bv.w;
            acc[3][0] += av.w * bv.x; acc[3][1] += av.w * bv.y; acc[3][2] += av.w * bv.z; acc[3][3] += av.w * bv.w;
        }
        __syncthreads();
    }
    #pragma unroll
    for (int i = 0; i < 4; i++) {
        float4 r = make_float4(acc[i][0], acc[i][1], acc[i][2], acc[i][3]);
        *(float4*)&C[(size_t)(m0 + ty * 4 + i) * N + n0 + tx * 4] = r;
    }
}

// ---------------- LayerNorm + exact GELU ----------------
__global__ void ln_gelu_kernel(const float* __restrict__ X, const float* __restrict__ b1,
                               const float* __restrict__ g, const float* __restrict__ b,
                               float* __restrict__ G)
{
    int row = blockIdx.x, t = threadIdx.x;
    float v = X[(size_t)row * DD + t] + b1[t];
    float mu = blockReduceSum256(v) * (1.0f / DD);
    float d = v - mu;
    float var = blockReduceSum256(d * d) * (1.0f / DD);
    float y = d * rsqrtf(var + EPSF) * g[t] + b[t];
    G[(size_t)row * DD + t] = 0.5f * y * (1.0f + erff(y * 0.7071067811865476f));
}

// ---------------- add bias + Poincare projection for queries (+ bf16 split) ----------------
__global__ void projq_kernel(const float* __restrict__ X, const float* __restrict__ b2,
                             __nv_bfloat16* __restrict__ qhi, __nv_bfloat16* __restrict__ qlo,
                             float* __restrict__ x2o, float* __restrict__ omx2o)
{
    int row = blockIdx.x, t = threadIdx.x;
    float v = X[(size_t)row * DD + t] + b2[t];
    float ss = blockReduceSum256(v * v);
    float norm = sqrtf(ss);
    float scale = (norm > MAXN) ? (MAXN / fmaxf(norm, EPSF)) : 1.0f;
    float y = v * scale;
    __nv_bfloat16 h = __float2bfloat16(y);
    qhi[(size_t)row * DD + t] = h;
    qlo[(size_t)row * DD + t] = __float2bfloat16(y - __bfloat162float(h));
    float y2 = blockReduceSum256(y * y);
    if (t == 0) { x2o[row] = y2; omx2o[row] = 1.0f - y2; }
}

// ---------------- memory bank projection (+ bf16 split) ----------------
__global__ void memprep_kernel(const float* __restrict__ mem, float* __restrict__ mb,
                               __nv_bfloat16* __restrict__ mhi, __nv_bfloat16* __restrict__ mlo,
                               float* __restrict__ y2o, float* __restrict__ omy2o)
{
    int row = blockIdx.x, t = threadIdx.x;
    float v = mem[(size_t)row * DD + t];
    float ss = blockReduceSum256(v * v);
    float norm = sqrtf(ss);
    float scale = (norm > MAXN) ? (MAXN / fmaxf(norm, EPSF)) : 1.0f;
    float y = v * scale;
    mb[(size_t)row * DD + t] = y;
    __nv_bfloat16 h = __float2bfloat16(y);
    mhi[(size_t)row * DD + t] = h;
    mlo[(size_t)row * DD + t] = __float2bfloat16(y - __bfloat162float(h));
    float y2 = blockReduceSum256(y * y);
    if (t == 0) { y2o[row] = y2; omy2o[row] = 1.0f - y2; }
}

// ---------------- fused distance GEMM (bf16-split tensor MMA) + per-query top-K ----------------
__global__ void __launch_bounds__(256, 1) topk_mma_kernel(
    const __nv_bfloat16* __restrict__ qhip, const __nv_bfloat16* __restrict__ qlop,
    const float* __restrict__ x2p, const float* __restrict__ omx2p,
    const __nv_bfloat16* __restrict__ mhip, const __nv_bfloat16* __restrict__ mlop,
    const float* __restrict__ y2p, const float* __restrict__ omy2p,
    float* __restrict__ pkey, int* __restrict__ pidx)
{
    extern __shared__ char smraw[];
    __nv_bfloat16* qshi = (__nv_bfloat16*)smraw;            // [64][QSTR]
    __nv_bfloat16* qslo = qshi + 64 * QSTR;
    __nv_bfloat16* mshi = qslo + 64 * QSTR;                 // [128][MSTR]
    __nv_bfloat16* mslo = mshi + 128 * MSTR;
    float* keyb  = (float*)(mslo + 128 * MSTR);             // [64][KSTR]
    float* lkey  = keyb + 64 * KSTR;                        // [64][KNN]
    int*   lidx  = (int*)(lkey + 64 * KNN);
    float* sx2   = (float*)(lidx + 64 * KNN);
    float* somx2 = sx2 + 64;
    float* sy2   = somx2 + 64;                              // [128]
    float* somy2 = sy2 + 128;

    int tid = threadIdx.x, lane = tid & 31, w = tid >> 5;
    int wq = w & 1, wm = w >> 1;
    int q0 = blockIdx.x * QB;
    int mbase = blockIdx.y * MSL;

    // load q block (hi+lo) into smem
    for (int i = tid; i < 64 * (DD / 8); i += 256) {
        int r = i >> 5, c = (i & 31) * 8;
        *(uint4*)&qshi[r * QSTR + c] = *(const uint4*)&qhip[(size_t)(q0 + r) * DD + c];
        *(uint4*)&qslo[r * QSTR + c] = *(const uint4*)&qlop[(size_t)(q0 + r) * DD + c];
    }
    if (tid < QB) {
        sx2[tid] = x2p[q0 + tid];
        somx2[tid] = omx2p[q0 + tid];
        #pragma unroll
        for (int j = 0; j < KNN; j++) { lkey[tid * KNN + j] = FINF; lidx[tid * KNN + j] = 0; }
    }

    uint32_t qbase = s2u(qshi);
    uint32_t qlbase = s2u(qslo);
    uint32_t mbase_hi = s2u(mshi);
    uint32_t mbase_lo = s2u(mslo);

    // per-lane ldmatrix address offsets (in elements)
    int a_row = wq * 32 + (lane & 15);          // + qf*16
    int a_col = (lane >> 4) << 3;               // + kc + ks
    int b_row = wm * 32 + (lane & 15);          // + bh*16
    int b_col = (lane >> 4) << 3;               // + ks

    for (int mt = 0; mt < MSL; mt += MT) {
        float acc[2][4][4];
        #pragma unroll
        for (int a = 0; a < 2; a++)
            #pragma unroll
            for (int b = 0; b < 4; b++)
                #pragma unroll
                for (int c = 0; c < 4; c++) acc[a][b][c] = 0.0f;

        for (int kc = 0; kc < DD; kc += 64) {
            __syncthreads();   // prev chunk mma done (and prev tile scan done for kc==0)
            {
                const __nv_bfloat16* gmh = mhip + (size_t)(mbase + mt) * DD + kc;
                const __nv_bfloat16* gml = mlop + (size_t)(mbase + mt) * DD + kc;
                for (int i = tid; i < 128 * 8; i += 256) {
                    int r = i >> 3, c = (i & 7) * 8;
                    *(uint4*)&mshi[r * MSTR + c] = *(const uint4*)&gmh[(size_t)r * DD + c];
                    *(uint4*)&mslo[r * MSTR + c] = *(const uint4*)&gml[(size_t)r * DD + c];
                }
                if (kc == 0 && tid < MT) {
                    sy2[tid] = y2p[mbase + mt + tid];
                    somy2[tid] = omy2p[mbase + mt + tid];
                }
            }
            __syncthreads();   // ms ready

            #pragma unroll
            for (int ks = 0; ks < 64; ks += 16) {
                uint32_t ahi[2][4], alo[2][4];
                uint32_t bh[4][2], bl[4][2];
                #pragma unroll
                for (int qf = 0; qf < 2; qf++) {
                    uint32_t off = (uint32_t)((a_row + qf * 16) * QSTR + kc + ks + a_col) * 2;
                    ldsm4(ahi[qf][0], ahi[qf][1], ahi[qf][2], ahi[qf][3], qbase + off);
                    ldsm4(alo[qf][0], alo[qf][1], alo[qf][2], alo[qf][3], qlbase + off);
                }
                #pragma unroll
                for (int bhx = 0; bhx < 2; bhx++) {
                    uint32_t off = (uint32_t)((b_row + bhx * 16) * MSTR + ks + b_col) * 2;
                    uint32_t r0, r1, r2, r3;
                    ldsm4(r0, r1, r2, r3, mbase_hi + off);
                    bh[bhx * 2 + 0][0] = r0; bh[bhx * 2 + 0][1] = r2;
                    bh[bhx * 2 + 1][0] = r1; bh[bhx * 2 + 1][1] = r3;
                    ldsm4(r0, r1, r2, r3, mbase_lo + off);
                    bl[bhx * 2 + 0][0] = r0; bl[bhx * 2 + 0][1] = r2;
                    bl[bhx * 2 + 1][0] = r1; bl[bhx * 2 + 1][1] = r3;
                }
                #pragma unroll
                for (int qf = 0; qf < 2; qf++) {
                    #pragma unroll
                    for (int mf = 0; mf < 4; mf++) {
                        mma_bf16(acc[qf][mf], ahi[qf], bh[mf][0], bh[mf][1]);  // hi*hi
                        mma_bf16(acc[qf][mf], ahi[qf], bl[mf][0], bl[mf][1]);  // hi*lo
                        mma_bf16(acc[qf][mf], alo[qf], bh[mf][0], bh[mf][1]);  // lo*hi
                    }
                }
            }
        }

        // keys into smem tile
        #pragma unroll
        for (int qf = 0; qf < 2; qf++) {
            int lq0 = wq * 32 + qf * 16 + (lane >> 2);
            #pragma unroll
            for (int mf = 0; mf < 4; mf++) {
                int lm0 = wm * 32 + mf * 8 + (lane & 3) * 2;
                #pragma unroll
                for (int c = 0; c < 4; c++) {
                    int lq = lq0 + (c >> 1) * 8;
                    int lm = lm0 + (c & 1);
                    float x2v = sx2[lq], y2v = sy2[lm];
                    float sq = fmaxf(x2v + y2v - 2.0f * acc[qf][mf][c], 0.0f);
                    float den = fmaxf(somx2[lq] * somy2[lm], EPSF);
                    keyb[lq * KSTR + lm] = sq / den;
                }
            }
        }
        __syncthreads();   // keyb ready

        // per-query sorted top-K update
        if (tid < QB) {
            float worst = lkey[tid * KNN + KNN - 1];
            for (int m = 0; m < MT; m++) {
                float kv = keyb[tid * KSTR + m];
                if (kv < worst) {
                    int pos = KNN - 1;
                    while (pos > 0 && lkey[tid * KNN + pos - 1] > kv) {
                        lkey[tid * KNN + pos] = lkey[tid * KNN + pos - 1];
                        lidx[tid * KNN + pos] = lidx[tid * KNN + pos - 1];
                        pos--;
                    }
                    lkey[tid * KNN + pos] = kv;
                    lidx[tid * KNN + pos] = mbase + mt + m;
                    worst = lkey[tid * KNN + KNN - 1];
                }
            }
        }
        // next iteration's first __syncthreads() orders scan vs next loads
    }
    __syncthreads();
    for (int i = tid; i < QB * KNN; i += 256) {
        int q = i / KNN, j = i % KNN;
        int o = ((q0 + q) * NSLICE + blockIdx.y) * KNN + j;
        pkey[o] = lkey[i];
        pidx[o] = lidx[i];
    }
}

// ---------------- merge partial top-K, arccosh, softmax, gather retrieved ----------------
__global__ void merge_kernel(const float* __restrict__ pkey, const int* __restrict__ pidx,
                             const float* __restrict__ mb, float* __restrict__ ret)
{
    int q = blockIdx.x, t = threadIdx.x;
    __shared__ float skey[256];
    __shared__ int   sidx[256];
    __shared__ float wkey[KNN];
    __shared__ int   widx[KNN];
    __shared__ float wgt[KNN];

    float myk = pkey[(size_t)q * 256 + t];
    int   myi = pidx[(size_t)q * 256 + t];

    for (int j = 0; j < KNN; j++) {
        skey[t] = myk; sidx[t] = myi;
        __syncthreads();
        for (int s = 128; s > 0; s >>= 1) {
            if (t < s) {
                float k2 = skey[t + s]; int i2 = sidx[t + s];
                if (k2 < skey[t] || (k2 == skey[t] && i2 < sidx[t])) { skey[t] = k2; sidx[t] = i2; }
            }
            __syncthreads();
        }
        if (t == 0) { wkey[j] = skey[0]; widx[j] = sidx[0]; }
        __syncthreads();
        if (myi == widx[j]) myk = FINF;   // indices globally unique
    }

    if (t == 0) {
        float dv[KNN];
        #pragma unroll
        for (int j = 0; j < KNN; j++) {
            float arg = fmaxf(1.0f + 2.0f * wkey[j], 1.0f + EPSF);
            dv[j] = logf(arg + sqrtf(arg * arg - 1.0f));    // arccosh
        }
        float dmin = dv[0];
        #pragma unroll
        for (int j = 1; j < KNN; j++) dmin = fminf(dmin, dv[j]);
        float s = 0.0f;
        #pragma unroll
        for (int j = 0; j < KNN; j++) { float e = expf(dmin - dv[j]); wgt[j] = e; s += e; }
        float inv = 1.0f / s;
        #pragma unroll
        for (int j = 0; j < KNN; j++) wgt[j] *= inv;
    }
    __syncthreads();

    float acc = 0.0f;
    #pragma unroll
    for (int j = 0; j < KNN; j++) acc += wgt[j] * mb[(size_t)widx[j] * DD + t];
    ret[(size_t)q * DD + t] = acc;
}

// ---------------- residual epilogue ----------------
__global__ void final_kernel(const float* __restrict__ hidden, const float* __restrict__ go,
                             const float* __restrict__ bp, float* __restrict__ out)
{
    int i = blockIdx.x * 256 + threadIdx.x;
    out[i] = hidden[i] + 0.1f * (go[i] + bp[i & (HID - 1)]);
}

// ---------------- launcher ----------------
extern "C" void kernel_launch(void* const* d_in, const int* in_sizes, int n_in,
                              void* d_out, int out_size)
{
    const float* hidden = (const float*)d_in[0];
    const float* memory = (const float*)d_in[1];
    const float* w1     = (const float*)d_in[2];
    const float* b1     = (const float*)d_in[3];
    const float* ln_g   = (const float*)d_in[4];
    const float* ln_b   = (const float*)d_in[5];
    const float* w2     = (const float*)d_in[6];
    const float* b2     = (const float*)d_in[7];
    const float* wp     = (const float*)d_in[8];
    const float* bp     = (const float*)d_in[9];
    float* out = (float*)d_out;

    float *tmp1, *G, *tmp2, *x2, *omx2, *mb, *y2, *omy2, *pkey, *ret, *tmp3;
    __nv_bfloat16 *qhi, *qlo, *mhi, *mlo;
    int* pidx;
    cudaGetSymbolAddress((void**)&tmp1, g_tmp1);
    cudaGetSymbolAddress((void**)&G,    g_G);
    cudaGetSymbolAddress((void**)&tmp2, g_tmp2);
    cudaGetSymbolAddress((void**)&qhi,  g_qhi);
    cudaGetSymbolAddress((void**)&qlo,  g_qlo);
    cudaGetSymbolAddress((void**)&x2,   g_x2);
    cudaGetSymbolAddress((void**)&omx2, g_omx2);
    cudaGetSymbolAddress((void**)&mb,   g_mb);
    cudaGetSymbolAddress((void**)&mhi,  g_mhi);
    cudaGetSymbolAddress((void**)&mlo,  g_mlo);
    cudaGetSymbolAddress((void**)&y2,   g_y2);
    cudaGetSymbolAddress((void**)&omy2, g_omy2);
    cudaGetSymbolAddress((void**)&pkey, g_pkey);
    cudaGetSymbolAddress((void**)&pidx, g_pidx);
    cudaGetSymbolAddress((void**)&ret,  g_ret);
    cudaGetSymbolAddress((void**)&tmp3, g_tmp3);

    const int SMEMB = (2 * 64 * QSTR + 2 * 128 * MSTR) * 2           // bf16 tiles
                    + (64 * KSTR + 64 * KNN) * 4 + 64 * KNN * 4      // keyb + lists
                    + (64 + 64 + 128 + 128) * 4;                     // scalars
    cudaFuncSetAttribute(topk_mma_kernel, cudaFuncAttributeMaxDynamicSharedMemorySize, SMEMB);

    // query network
    gemm64x64<<<dim3(NQ / 64, DD / 64), 256>>>(hidden, w1, tmp1, NQ, DD, HID);
    ln_gelu_kernel<<<NQ, 256>>>(tmp1, b1, ln_g, ln_b, G);
    gemm64x64<<<dim3(NQ / 64, DD / 64), 256>>>(G, w2, tmp2, NQ, DD, DD);
    projq_kernel<<<NQ, 256>>>(tmp2, b2, qhi, qlo, x2, omx2);

    // memory bank projection + bf16 split
    memprep_kernel<<<MM, 256>>>(memory, mb, mhi, mlo, y2, omy2);

    // fused distance + top-K over M slices (tensor cores)
    topk_mma_kernel<<<dim3(NQ / QB, NSLICE), 256, SMEMB>>>(qhi, qlo, x2, omx2, mhi, mlo, y2, omy2, pkey, pidx);

    // merge + softmax + weighted gather
    merge_kernel<<<NQ, 256>>>(pkey, pidx, mb, ret);

    // project back + residual
    gemm64x64<<<dim3(NQ / 64, HID / 64), 256>>>(ret, wp, tmp3, NQ, HID, DD);
    final_kernel<<<NQ * HID / 256, 256>>>(hidden, tmp3, bp, out);
}

// round 3
// speedup vs baseline: 1.0010x; 1.0010x over previous
#include <cuda_runtime.h>
#include <cuda_bf16.h>
#include <math.h>
#include <stdint.h>

#define EPSF  1e-5f
#define MAXN  0.99999f
#define NQ    2048
#define HID   1024
#define DD    256
#define MM    65536
#define KNN   16
#define NSLICE 16
#define MSL   (MM / NSLICE)
#define QB    64
#define MT    128
#define KCH   32
#define FINF  3.402823466e38f

#define QSTR 264   // q smem row stride (bf16 elems)
#define MSTR 72    // m smem row stride (bf16 elems)
#define KSTR 129   // key smem row stride (f32 elems)

// ---------------- device scratch (no cudaMalloc allowed) ----------------
__device__ float g_tmp1[NQ * DD];
__device__ float g_G[NQ * DD];
__device__ float g_tmp2[NQ * DD];
__device__ float g_x2[NQ];
__device__ float g_omx2[NQ];
__device__ __nv_bfloat16 g_qhi[NQ * DD];
__device__ __nv_bfloat16 g_qlo[NQ * DD];
__device__ float g_mb[(size_t)MM * DD];             // 64 MB projected memory bank (fp32, for gather)
__device__ __nv_bfloat16 g_mhi[(size_t)MM * DD];    // 32 MB
__device__ __nv_bfloat16 g_mlo[(size_t)MM * DD];    // 32 MB
__device__ float g_y2[MM];
__device__ float g_omy2[MM];
__device__ float g_pkey[NQ * NSLICE * KNN];
__device__ int   g_pidx[NQ * NSLICE * KNN];
__device__ float g_ret[NQ * DD];
__device__ float g_tmp3[NQ * HID];

// ---------------- helpers ----------------
__device__ __forceinline__ float blockReduceSum256(float v) {
    __shared__ float sred[8];
    #pragma unroll
    for (int o = 16; o > 0; o >>= 1) v += __shfl_down_sync(0xffffffffu, v, o);
    int w = threadIdx.x >> 5;
    if ((threadIdx.x & 31) == 0) sred[w] = v;
    __syncthreads();
    if (threadIdx.x < 32) {
        float r = (threadIdx.x < 8) ? sred[threadIdx.x] : 0.0f;
        #pragma unroll
        for (int o = 4; o > 0; o >>= 1) r += __shfl_down_sync(0xffffffffu, r, o);
        if (threadIdx.x == 0) sred[0] = r;
    }
    __syncthreads();
    float r = sred[0];
    __syncthreads();
    return r;
}

__device__ __forceinline__ uint32_t s2u(const void* p) {
    return (uint32_t)__cvta_generic_to_shared(p);
}

__device__ __forceinline__ void ldsm4(uint32_t& r0, uint32_t& r1, uint32_t& r2, uint32_t& r3, uint32_t addr) {
    asm volatile("ldmatrix.sync.aligned.m8n8.x4.shared.b16 {%0,%1,%2,%3}, [%4];"
                 : "=r"(r0), "=r"(r1), "=r"(r2), "=r"(r3) : "r"(addr));
}

__device__ __forceinline__ void mma_bf16(float (&d)[4], const uint32_t (&a)[4], uint32_t b0, uint32_t b1) {
    asm volatile("mma.sync.aligned.m16n8k16.row.col.f32.bf16.bf16.f32 "
                 "{%0,%1,%2,%3}, {%4,%5,%6,%7}, {%8,%9}, {%0,%1,%2,%3};"
                 : "+f"(d[0]), "+f"(d[1]), "+f"(d[2]), "+f"(d[3])
                 : "r"(a[0]), "r"(a[1]), "r"(a[2]), "r"(a[3]), "r"(b0), "r"(b1));
}

// ---------------- generic 64x64 tiled fp32 GEMM: C = A[MxK] @ B[KxN] ----------------
__global__ void __launch_bounds__(256) gemm64x64(
    const float* __restrict__ A, const float* __restrict__ B,
    float* __restrict__ C, int M, int N, int Kd)
{
    __shared__ float As[KCH * 68];
    __shared__ float Bs[KCH * 68];
    int tid = threadIdx.x;
    int tx = tid & 15, ty = tid >> 4;
    int m0 = blockIdx.x * 64, n0 = blockIdx.y * 64;
    float acc[4][4] = {};
    for (int k0 = 0; k0 < Kd; k0 += KCH) {
        for (int i = tid; i < 64 * KCH; i += 256) {
            int m = i >> 5, k = i & 31;
            As[k * 68 + m] = A[(size_t)(m0 + m) * Kd + k0 + k];
        }
        for (int i = tid; i < KCH * 64; i += 256) {
            int k = i >> 6, n = i & 63;
            Bs[k * 68 + n] = B[(size_t)(k0 + k) * N + n0 + n];
        }
        __syncthreads();
        #pragma unroll
        for (int k = 0; k < KCH; k++) {
            float4 bv = *(const float4*)&Bs[k * 68 + tx * 4];
            float4 av = *(const float4*)&As[k * 68 + ty * 4];
            acc[0][0] += av.x * bv.x; acc[0][1] += av.x * bv.y; acc[0][2] += av.x * bv.z; acc[0][3] += av.x * bv.w;
            acc[1][0] += av.y * bv.x; acc[1][1] += av.y * bv.y; acc[1][2] += av.y * bv.z; acc[1][3] += av.y * bv.w;
            acc[2][0] += av.z * bv.x; acc[2][1] += av.z * bv.y; acc[2][2] += av.z * bv.z; acc[2][3] += av.z * bv.w;
            acc[3][0] += av.w * bv.x; acc[3][1] += av.w * bv.y; acc[3][2] += av.w * bv.z; acc[3][3] += av.w * bv.w;
        }
        __syncthreads();
    }
    #pragma unroll
    for (int i = 0; i < 4; i++) {
        float4 r = make_float4(acc[i][0], acc[i][1], acc[i][2], acc[i][3]);
        *(float4*)&C[(size_t)(m0 + ty * 4 + i) * N + n0 + tx * 4] = r;
    }
}

// ---------------- LayerNorm + exact GELU ----------------
__global__ void ln_gelu_kernel(const float* __restrict__ X, const float* __restrict__ b1,
                               const float* __restrict__ g, const float* __restrict__ b,
                               float* __restrict__ G)
{
    int row = blockIdx.x, t = threadIdx.x;
    float v = X[(size_t)row * DD + t] + b1[t];
    float mu = blockReduceSum256(v) * (1.0f / DD);
    float d = v - mu;
    float var = blockReduceSum256(d * d) * (1.0f / DD);
    float y = d * rsqrtf(var + EPSF) * g[t] + b[t];
    G[(size_t)row * DD + t] = 0.5f * y * (1.0f + erff(y * 0.7071067811865476f));
}

// ---------------- add bias + Poincare projection for queries (+ bf16 split) ----------------
__global__ void projq_kernel(const float* __restrict__ X, const float* __restrict__ b2,
                             __nv_bfloat16* __restrict__ qhi, __nv_bfloat16* __restrict__ qlo,
                             float* __restrict__ x2o, float* __restrict__ omx2o)
{
    int row = blockIdx.x, t = threadIdx.x;
    float v = X[(size_t)row * DD + t] + b2[t];
    float ss = blockReduceSum256(v * v);
    float norm = sqrtf(ss);
    float scale = (norm > MAXN) ? (MAXN / fmaxf(norm, EPSF)) : 1.0f;
    float y = v * scale;
    __nv_bfloat16 h = __float2bfloat16(y);
    qhi[(size_t)row * DD + t] = h;
    qlo[(size_t)row * DD + t] = __float2bfloat16(y - __bfloat162float(h));
    float y2 = blockReduceSum256(y * y);
    if (t == 0) { x2o[row] = y2; omx2o[row] = 1.0f - y2; }
}

// ---------------- memory bank projection (+ bf16 split) ----------------
__global__ void memprep_kernel(const float* __restrict__ mem, float* __restrict__ mb,
                               __nv_bfloat16* __restrict__ mhi, __nv_bfloat16* __restrict__ mlo,
                               float* __restrict__ y2o, float* __restrict__ omy2o)
{
    int row = blockIdx.x, t = threadIdx.x;
    float v = mem[(size_t)row * DD + t];
    float ss = blockReduceSum256(v * v);
    float norm = sqrtf(ss);
    float scale = (norm > MAXN) ? (MAXN / fmaxf(norm, EPSF)) : 1.0f;
    float y = v * scale;
    mb[(size_t)row * DD + t] = y;
    __nv_bfloat16 h = __float2bfloat16(y);
    mhi[(size_t)row * DD + t] = h;
    mlo[(size_t)row * DD + t] = __float2bfloat16(y - __bfloat162float(h));
    float y2 = blockReduceSum256(y * y);
    if (t == 0) { y2o[row] = y2; omy2o[row] = 1.0f - y2; }
}

// ---------------- fused distance GEMM (bf16-split tensor MMA) + per-query top-K ----------------
__global__ void __launch_bounds__(256, 1) topk_mma_kernel(
    const __nv_bfloat16* __restrict__ qhip, const __nv_bfloat16* __restrict__ qlop,
    const float* __restrict__ x2p, const float* __restrict__ omx2p,
    const __nv_bfloat16* __restrict__ mhip, const __nv_bfloat16* __restrict__ mlop,
    const float* __restrict__ y2p, const float* __restrict__ omy2p,
    float* __restrict__ pkey, int* __restrict__ pidx)
{
    extern __shared__ char smraw[];
    __nv_bfloat16* qshi = (__nv_bfloat16*)smraw;            // [64][QSTR]
    __nv_bfloat16* qslo = qshi + 64 * QSTR;
    __nv_bfloat16* mshi = qslo + 64 * QSTR;                 // [128][MSTR]
    __nv_bfloat16* mslo = mshi + 128 * MSTR;
    float* keyb  = (float*)(mslo + 128 * MSTR);             // [64][KSTR]
    float* lkey  = keyb + 64 * KSTR;                        // [64][KNN]
    int*   lidx  = (int*)(lkey + 64 * KNN);
    float* sx2   = (float*)(lidx + 64 * KNN);
    float* somx2 = sx2 + 64;
    float* sy2   = somx2 + 64;                              // [128]
    float* somy2 = sy2 + 128;

    int tid = threadIdx.x, lane = tid & 31, w = tid >> 5;
    int wq = w & 1, wm = w >> 1;
    int q0 = blockIdx.x * QB;
    int mbase = blockIdx.y * MSL;

    // load q block (hi+lo) into smem
    for (int i = tid; i < 64 * (DD / 8); i += 256) {
        int r = i >> 5, c = (i & 31) * 8;
        *(uint4*)&qshi[r * QSTR + c] = *(const uint4*)&qhip[(size_t)(q0 + r) * DD + c];
        *(uint4*)&qslo[r * QSTR + c] = *(const uint4*)&qlop[(size_t)(q0 + r) * DD + c];
    }
    if (tid < QB) {
        sx2[tid] = x2p[q0 + tid];
        somx2[tid] = omx2p[q0 + tid];
        #pragma unroll
        for (int j = 0; j < KNN; j++) { lkey[tid * KNN + j] = FINF; lidx[tid * KNN + j] = 0; }
    }

    uint32_t qbase = s2u(qshi);
    uint32_t qlbase = s2u(qslo);
    uint32_t mbase_hi = s2u(mshi);
    uint32_t mbase_lo = s2u(mslo);

    // per-lane ldmatrix address offsets (in elements)
    int a_row = wq * 32 + (lane & 15);          // + qf*16
    int a_col = (lane >> 4) << 3;               // + kc + ks
    int b_row = wm * 32 + (lane & 15);          // + bh*16
    int b_col = (lane >> 4) << 3;               // + ks

    for (int mt = 0; mt < MSL; mt += MT) {
        float acc[2][4][4];
        #pragma unroll
        for (int a = 0; a < 2; a++)
            #pragma unroll
            for (int b = 0; b < 4; b++)
                #pragma unroll
                for (int c = 0; c < 4; c++) acc[a][b][c] = 0.0f;

        for (int kc = 0; kc < DD; kc += 64) {
            __syncthreads();   // prev chunk mma done (and prev tile scan done for kc==0)
            {
                const __nv_bfloat16* gmh = mhip + (size_t)(mbase + mt) * DD + kc;
                const __nv_bfloat16* gml = mlop + (size_t)(mbase + mt) * DD + kc;
                for (int i = tid; i < 128 * 8; i += 256) {
                    int r = i >> 3, c = (i & 7) * 8;
                    *(uint4*)&mshi[r * MSTR + c] = *(const uint4*)&gmh[(size_t)r * DD + c];
                    *(uint4*)&mslo[r * MSTR + c] = *(const uint4*)&gml[(size_t)r * DD + c];
                }
                if (kc == 0 && tid < MT) {
                    sy2[tid] = y2p[mbase + mt + tid];
                    somy2[tid] = omy2p[mbase + mt + tid];
                }
            }
            __syncthreads();   // ms ready

            #pragma unroll
            for (int ks = 0; ks < 64; ks += 16) {
                uint32_t ahi[2][4], alo[2][4];
                uint32_t bh[4][2], bl[4][2];
                #pragma unroll
                for (int qf = 0; qf < 2; qf++) {
                    uint32_t off = (uint32_t)((a_row + qf * 16) * QSTR + kc + ks + a_col) * 2;
                    ldsm4(ahi[qf][0], ahi[qf][1], ahi[qf][2], ahi[qf][3], qbase + off);
                    ldsm4(alo[qf][0], alo[qf][1], alo[qf][2], alo[qf][3], qlbase + off);
                }
                #pragma unroll
                for (int bhx = 0; bhx < 2; bhx++) {
                    uint32_t off = (uint32_t)((b_row + bhx * 16) * MSTR + ks + b_col) * 2;
                    uint32_t r0, r1, r2, r3;
                    ldsm4(r0, r1, r2, r3, mbase_hi + off);
                    bh[bhx * 2 + 0][0] = r0; bh[bhx * 2 + 0][1] = r2;
                    bh[bhx * 2 + 1][0] = r1; bh[bhx * 2 + 1][1] = r3;
                    ldsm4(r0, r1, r2, r3, mbase_lo + off);
                    bl[bhx * 2 + 0][0] = r0; bl[bhx * 2 + 0][1] = r2;
                    bl[bhx * 2 + 1][0] = r1; bl[bhx * 2 + 1][1] = r3;
                }
                #pragma unroll
                for (int qf = 0; qf < 2; qf++) {
                    #pragma unroll
                    for (int mf = 0; mf < 4; mf++) {
                        mma_bf16(acc[qf][mf], ahi[qf], bh[mf][0], bh[mf][1]);  // hi*hi
                        mma_bf16(acc[qf][mf], ahi[qf], bl[mf][0], bl[mf][1]);  // hi*lo
                        mma_bf16(acc[qf][mf], alo[qf], bh[mf][0], bh[mf][1]);  // lo*hi
                    }
                }
            }
        }

        // keys into smem tile
        #pragma unroll
        for (int qf = 0; qf < 2; qf++) {
            int lq0 = wq * 32 + qf * 16 + (lane >> 2);
            #pragma unroll
            for (int mf = 0; mf < 4; mf++) {
                int lm0 = wm * 32 + mf * 8 + (lane & 3) * 2;
                #pragma unroll
                for (int c = 0; c < 4; c++) {
                    int lq = lq0 + (c >> 1) * 8;
                    int lm = lm0 + (c & 1);
                    float x2v = sx2[lq], y2v = sy2[lm];
                    float sq = fmaxf(x2v + y2v - 2.0f * acc[qf][mf][c], 0.0f);
                    float den = fmaxf(somx2[lq] * somy2[lm], EPSF);
                    keyb[lq * KSTR + lm] = sq / den;
                }
            }
        }
        __syncthreads();   // keyb ready

        // per-query sorted top-K update
        if (tid < QB) {
            float worst = lkey[tid * KNN + KNN - 1];
            for (int m = 0; m < MT; m++) {
                float kv = keyb[tid * KSTR + m];
                if (kv < worst) {
                    int pos = KNN - 1;
                    while (pos > 0 && lkey[tid * KNN + pos - 1] > kv) {
                        lkey[tid * KNN + pos] = lkey[tid * KNN + pos - 1];
                        lidx[tid * KNN + pos] = lidx[tid * KNN + pos - 1];
                        pos--;
                    }
                    lkey[tid * KNN + pos] = kv;
                    lidx[tid * KNN + pos] = mbase + mt + m;
                    worst = lkey[tid * KNN + KNN - 1];
                }
            }
        }
        // next iteration's first __syncthreads() orders scan vs next loads
    }
    __syncthreads();
    for (int i = tid; i < QB * KNN; i += 256) {
        int q = i / KNN, j = i % KNN;
        int o = ((q0 + q) * NSLICE + blockIdx.y) * KNN + j;
        pkey[o] = lkey[i];
        pidx[o] = lidx[i];
    }
}

// ---------------- merge partial top-K, arccosh, softmax, gather retrieved ----------------
__global__ void merge_kernel(const float* __restrict__ pkey, const int* __restrict__ pidx,
                             const float* __restrict__ mb, float* __restrict__ ret)
{
    int q = blockIdx.x, t = threadIdx.x;
    __shared__ float skey[256];
    __shared__ int   sidx[256];
    __shared__ float wkey[KNN];
    __shared__ int   widx[KNN];
    __shared__ float wgt[KNN];

    float myk = pkey[(size_t)q * 256 + t];
    int   myi = pidx[(size_t)q * 256 + t];

    for (int j = 0; j < KNN; j++) {
        skey[t] = myk; sidx[t] = myi;
        __syncthreads();
        for (int s = 128; s > 0; s >>= 1) {
            if (t < s) {
                float k2 = skey[t + s]; int i2 = sidx[t + s];
                if (k2 < skey[t] || (k2 == skey[t] && i2 < sidx[t])) { skey[t] = k2; sidx[t] = i2; }
            }
            __syncthreads();
        }
        if (t == 0) { wkey[j] = skey[0]; widx[j] = sidx[0]; }
        __syncthreads();
        if (myi == widx[j]) myk = FINF;   // indices globally unique
    }

    if (t == 0) {
        float dv[KNN];
        #pragma unroll
        for (int j = 0; j < KNN; j++) {
            float arg = fmaxf(1.0f + 2.0f * wkey[j], 1.0f + EPSF);
            dv[j] = logf(arg + sqrtf(arg * arg - 1.0f));    // arccosh
        }
        float dmin = dv[0];
        #pragma unroll
        for (int j = 1; j < KNN; j++) dmin = fminf(dmin, dv[j]);
        float s = 0.0f;
        #pragma unroll
        for (int j = 0; j < KNN; j++) { float e = expf(dmin - dv[j]); wgt[j] = e; s += e; }
        float inv = 1.0f / s;
        #pragma unroll
        for (int j = 0; j < KNN; j++) wgt[j] *= inv;
    }
    __syncthreads();

    float acc = 0.0f;
    #pragma unroll
    for (int j = 0; j < KNN; j++) acc += wgt[j] * mb[(size_t)widx[j] * DD + t];
    ret[(size_t)q * DD + t] = acc;
}

// ---------------- residual epilogue ----------------
__global__ void final_kernel(const float* __restrict__ hidden, const float* __restrict__ go,
                             const float* __restrict__ bp, float* __restrict__ out)
{
    int i = blockIdx.x * 256 + threadIdx.x;
    out[i] = hidden[i] + 0.1f * (go[i] + bp[i & (HID - 1)]);
}

// ---------------- launcher ----------------
extern "C" void kernel_launch(void* const* d_in, const int* in_sizes, int n_in,
                              void* d_out, int out_size)
{
    const float* hidden = (const float*)d_in[0];
    const float* memory = (const float*)d_in[1];
    const float* w1     = (const float*)d_in[2];
    const float* b1     = (const float*)d_in[3];
    const float* ln_g   = (const float*)d_in[4];
    const float* ln_b   = (const float*)d_in[5];
    const float* w2     = (const float*)d_in[6];
    const float* b2     = (const float*)d_in[7];
    const float* wp     = (const float*)d_in[8];
    const float* bp     = (const float*)d_in[9];
    float* out = (float*)d_out;

    float *tmp1, *G, *tmp2, *x2, *omx2, *mb, *y2, *omy2, *pkey, *ret, *tmp3;
    __nv_bfloat16 *qhi, *qlo, *mhi, *mlo;
    int* pidx;
    cudaGetSymbolAddress((void**)&tmp1, g_tmp1);
    cudaGetSymbolAddress((void**)&G,    g_G);
    cudaGetSymbolAddress((void**)&tmp2, g_tmp2);
    cudaGetSymbolAddress((void**)&qhi,  g_qhi);
    cudaGetSymbolAddress((void**)&qlo,  g_qlo);
    cudaGetSymbolAddress((void**)&x2,   g_x2);
    cudaGetSymbolAddress((void**)&omx2, g_omx2);
    cudaGetSymbolAddress((void**)&mb,   g_mb);
    cudaGetSymbolAddress((void**)&mhi,  g_mhi);
    cudaGetSymbolAddress((void**)&mlo,  g_mlo);
    cudaGetSymbolAddress((void**)&y2,   g_y2);
    cudaGetSymbolAddress((void**)&omy2, g_omy2);
    cudaGetSymbolAddress((void**)&pkey, g_pkey);
    cudaGetSymbolAddress((void**)&pidx, g_pidx);
    cudaGetSymbolAddress((void**)&ret,  g_ret);
    cudaGetSymbolAddress((void**)&tmp3, g_tmp3);

    const int SMEMB = (2 * 64 * QSTR + 2 * 128 * MSTR) * 2           // bf16 tiles
                    + (64 * KSTR + 64 * KNN) * 4 + 64 * KNN * 4      // keyb + lists
                    + (64 + 64 + 128 + 128) * 4;                     // scalars
    cudaFuncSetAttribute(topk_mma_kernel, cudaFuncAttributeMaxDynamicSharedMemorySize, SMEMB);

    // query network
    gemm64x64<<<dim3(NQ / 64, DD / 64), 256>>>(hidden, w1, tmp1, NQ, DD, HID);
    ln_gelu_kernel<<<NQ, 256>>>(tmp1, b1, ln_g, ln_b, G);
    gemm64x64<<<dim3(NQ / 64, DD / 64), 256>>>(G, w2, tmp2, NQ, DD, DD);
    projq_kernel<<<NQ, 256>>>(tmp2, b2, qhi, qlo, x2, omx2);

    // memory bank projection + bf16 split
    memprep_kernel<<<MM, 256>>>(memory, mb, mhi, mlo, y2, omy2);

    // fused distance + top-K over M slices (tensor cores)
    topk_mma_kernel<<<dim3(NQ / QB, NSLICE), 256, SMEMB>>>(qhi, qlo, x2, omx2, mhi, mlo, y2, omy2, pkey, pidx);

    // merge + softmax + weighted gather
    merge_kernel<<<NQ, 256>>>(pkey, pidx, mb, ret);

    // project back + residual
    gemm64x64<<<dim3(NQ / 64, HID / 64), 256>>>(ret, wp, tmp3, NQ, HID, DD);
    final_kernel<<<NQ * HID / 256, 256>>>(hidden, tmp3, bp, out);
}

// round 5
// speedup vs baseline: 3.1247x; 3.1217x over previous
#include <cuda_runtime.h>
#include <cuda_bf16.h>
#include <math.h>
#include <stdint.h>

#define EPSF  1e-5f
#define MAXN  0.99999f
#define NQ    2048
#define HID   1024
#define DD    256
#define MM    65536
#define KNN   16
#define NSLICE 8
#define MSL   (MM / NSLICE)
#define QT    128
#define MT    64
#define TILES (MSL / MT)
#define KCH   32
#define FINF  3.402823466e38f
#define CAND  (NSLICE * KNN)

#define IDESC 0x8100490u

// smem layout (bytes) for topk kernel
#define OFF_TM   0
#define OFF_BAR  8
#define OFF_Y2   128
#define OFF_B    1024
#define BSTAGE   65536
#define OFF_LKEY 132096
#define OFF_LIDX 140288
#define SMEMB    148480

// tcgen05 availability guard: only arch/family-specific passes may emit it
#if defined(__CUDA_ARCH_FEAT_SM103_ALL) || defined(__CUDA_ARCH_FEAT_SM100_ALL) || \
    defined(__CUDA_ARCH_FEAT_SM101_ALL) || defined(__CUDA_ARCH_FEAT_SM110_ALL) || \
    (defined(__CUDA_ARCH_SPECIFIC__) && (__CUDA_ARCH_SPECIFIC__ >= 1000)) || \
    (defined(__CUDA_ARCH_FAMILY_SPECIFIC__) && (__CUDA_ARCH_FAMILY_SPECIFIC__ >= 1000))
#define USE_TC5 1
#else
#define USE_TC5 0
#endif

// ---------------- device scratch ----------------
__device__ float g_tmp1[NQ * DD];
__device__ float g_G[NQ * DD];
__device__ float g_tmp2[NQ * DD];
__device__ float g_qb[NQ * DD];
__device__ float g_x2[NQ];
__device__ __nv_bfloat16 g_qhi[NQ * DD];
__device__ __nv_bfloat16 g_qlo[NQ * DD];
__device__ float g_mb[(size_t)MM * DD];
__device__ __nv_bfloat16 g_mhi[(size_t)MM * DD];
__device__ __nv_bfloat16 g_mlo[(size_t)MM * DD];
__device__ float g_y2[MM];
__device__ float g_pkey[NQ * CAND];
__device__ int   g_pidx[NQ * CAND];
__device__ float g_ret[NQ * DD];
__device__ float g_tmp3[NQ * HID];

// ---------------- helpers ----------------
__device__ __forceinline__ uint32_t s2u(const void* p) {
    return (uint32_t)__cvta_generic_to_shared(p);
}
__device__ __forceinline__ float warpSum(float v) {
    #pragma unroll
    for (int o = 16; o > 0; o >>= 1) v += __shfl_xor_sync(0xffffffffu, v, o);
    return v;
}
__device__ __forceinline__ float blockReduceSum256(float v) {
    __shared__ float sred[8];
    v = warpSum(v);
    int w = threadIdx.x >> 5;
    if ((threadIdx.x & 31) == 0) sred[w] = v;
    __syncthreads();
    float r = (threadIdx.x < 8) ? sred[threadIdx.x] : 0.0f;
    if (threadIdx.x < 32) r = warpSum(r);
    if (threadIdx.x == 0) sred[0] = r;
    __syncthreads();
    r = sred[0];
    __syncthreads();
    return r;
}
__device__ __forceinline__ uint32_t packbf2(float a, float b) {
    __nv_bfloat162 t;
    t.x = __float2bfloat16(a);
    t.y = __float2bfloat16(b);
    return *(uint32_t*)&t;
}

#if USE_TC5
__device__ __forceinline__ uint32_t elect_one_pred() {
    uint32_t pred;
    asm volatile("{\n\t.reg .pred p;\n\telect.sync _|p, 0xFFFFFFFF;\n\tselp.b32 %0, 1, 0, p;\n\t}" : "=r"(pred));
    return pred;
}
#define TCGEN05_ALLOC(smem_addr, nCols) \
    asm volatile("tcgen05.alloc.cta_group::1.sync.aligned.shared::cta.b32 [%0], %1;" \
                 :: "r"((uint32_t)(smem_addr)), "r"((uint32_t)(nCols)) : "memory")
#define TCGEN05_DEALLOC(tmem_addr, nCols) \
    asm volatile("tcgen05.dealloc.cta_group::1.sync.aligned.b32 %0, %1;" :: "r"(tmem_addr), "r"((uint32_t)(nCols)))
#define TCGEN05_WAIT_ST() asm volatile("tcgen05.wait::st.sync.aligned;" ::: "memory")
#define TCGEN05_WAIT_LD() asm volatile("tcgen05.wait::ld.sync.aligned;" ::: "memory")
#define TCGEN05_FENCE_BEFORE() asm volatile("tcgen05.fence::before_thread_sync;" ::: "memory")
#define TCGEN05_FENCE_AFTER()  asm volatile("tcgen05.fence::after_thread_sync;" ::: "memory")
#define TCGEN05_COMMIT(mbar) \
    asm volatile("tcgen05.commit.cta_group::1.mbarrier::arrive::one.shared::cluster.b64 [%0];" \
                 :: "r"((uint32_t)(mbar)) : "memory")
#define FENCE_PROXY_ASYNC() asm volatile("fence.proxy.async.shared::cta;" ::: "memory")
#define MBARRIER_INIT(addr, cnt) \
    asm volatile("mbarrier.init.shared.b64 [%0], %1;" :: "r"((uint32_t)(addr)), "r"((uint32_t)(cnt)) : "memory")
#define MBARRIER_ARRIVE(addr) \
    asm volatile("mbarrier.arrive.shared.b64 _, [%0];" :: "r"((uint32_t)(addr)) : "memory")
#define MBARRIER_WAIT_PARITY(mbar_addr, phase_parity) do { \
    uint32_t _mbar = (uint32_t)(mbar_addr); \
    uint32_t _parity = (uint32_t)(phase_parity); \
    uint32_t _done; \
    asm volatile("{\n\t.reg .pred p;\n\t" \
        "mbarrier.try_wait.parity.acquire.cta.shared::cta.b64 p, [%1], %2;\n\t" \
        "selp.b32 %0, 1, 0, p;\n\t}" : "=r"(_done) : "r"(_mbar), "r"(_parity) : "memory"); \
    if (!_done) { \
        asm volatile("{\n\t.reg .pred P1;\n\t" \
            "WAIT_LOOP_%=:\n\t" \
            "mbarrier.try_wait.parity.acquire.cta.shared::cta.b64 P1, [%0], %1, 0x989680;\n\t" \
            "@P1 bra.uni WAIT_DONE_%=;\n\t" \
            "bra.uni WAIT_LOOP_%=;\n\t" \
            "WAIT_DONE_%=:\n\t}" :: "r"(_mbar), "r"(_parity) : "memory"); \
    } \
} while (0)

static constexpr uint64_t SMEM_DESC_BASE_SW128 =
    (uint64_t(2) << 61) | (uint64_t(1) << 46) | (uint64_t(64) << 32) | (uint64_t(1) << 16);
#define MAKE_SMEM_DESC(base_addr) (SMEM_DESC_BASE_SW128 | ((uint64_t)((base_addr) >> 4) & 0x3FFF))

#define TCGEN05_MMA_F16_TS(d_tmem, a_tmem, b_desc, idesc, en) do { \
    uint32_t _e = (uint32_t)(en); uint32_t _z = 0u; \
    asm volatile("{\n\t.reg .pred p;\n\tsetp.ne.u32 p, %5, 0;\n\t" \
        "tcgen05.mma.cta_group::1.kind::f16 [%0], [%1], %2, %3, {%4, %4, %4, %4}, p;\n\t}" \
        :: "r"(d_tmem), "r"(a_tmem), "l"(b_desc), "r"(idesc), "r"(_z), "r"(_e) : "memory"); \
} while (0)

#define TCGEN05_LD_X32(r, tmem_addr) \
    asm volatile("tcgen05.ld.sync.aligned.32x32b.x32.b32 " \
        "{%0, %1, %2, %3, %4, %5, %6, %7, %8, %9, %10, %11, %12, %13, %14, %15, " \
        " %16, %17, %18, %19, %20, %21, %22, %23, %24, %25, %26, %27, %28, %29, %30, %31}, [%32];" \
        : "=r"((r)[0]),  "=r"((r)[1]),  "=r"((r)[2]),  "=r"((r)[3]), \
          "=r"((r)[4]),  "=r"((r)[5]),  "=r"((r)[6]),  "=r"((r)[7]), \
          "=r"((r)[8]),  "=r"((r)[9]),  "=r"((r)[10]), "=r"((r)[11]), \
          "=r"((r)[12]), "=r"((r)[13]), "=r"((r)[14]), "=r"((r)[15]), \
          "=r"((r)[16]), "=r"((r)[17]), "=r"((r)[18]), "=r"((r)[19]), \
          "=r"((r)[20]), "=r"((r)[21]), "=r"((r)[22]), "=r"((r)[23]), \
          "=r"((r)[24]), "=r"((r)[25]), "=r"((r)[26]), "=r"((r)[27]), \
          "=r"((r)[28]), "=r"((r)[29]), "=r"((r)[30]), "=r"((r)[31]) \
        : "r"(tmem_addr))

#define TCGEN05_ST_X32(tmem_addr, r) \
    asm volatile("tcgen05.st.sync.aligned.32x32b.x32.b32 [%0], " \
        "{%1, %2, %3, %4, %5, %6, %7, %8, %9, %10, %11, %12, %13, %14, %15, %16, " \
        " %17, %18, %19, %20, %21, %22, %23, %24, %25, %26, %27, %28, %29, %30, %31, %32};" \
        :: "r"(tmem_addr), \
           "r"((r)[0]),  "r"((r)[1]),  "r"((r)[2]),  "r"((r)[3]), \
           "r"((r)[4]),  "r"((r)[5]),  "r"((r)[6]),  "r"((r)[7]), \
           "r"((r)[8]),  "r"((r)[9]),  "r"((r)[10]), "r"((r)[11]), \
           "r"((r)[12]), "r"((r)[13]), "r"((r)[14]), "r"((r)[15]), \
           "r"((r)[16]), "r"((r)[17]), "r"((r)[18]), "r"((r)[19]), \
           "r"((r)[20]), "r"((r)[21]), "r"((r)[22]), "r"((r)[23]), \
           "r"((r)[24]), "r"((r)[25]), "r"((r)[26]), "r"((r)[27]), \
           "r"((r)[28]), "r"((r)[29]), "r"((r)[30]), "r"((r)[31]) \
        : "memory")
#endif // USE_TC5

// ---------------- generic 64x64 tiled fp32 GEMM ----------------
__global__ void __launch_bounds__(256) gemm64x64(
    const float* __restrict__ A, const float* __restrict__ B,
    float* __restrict__ C, int M, int N, int Kd)
{
    __shared__ float As[KCH * 68];
    __shared__ float Bs[KCH * 68];
    int tid = threadIdx.x;
    int tx = tid & 15, ty = tid >> 4;
    int m0 = blockIdx.x * 64, n0 = blockIdx.y * 64;
    float acc[4][4] = {};
    for (int k0 = 0; k0 < Kd; k0 += KCH) {
        for (int i = tid; i < 64 * KCH; i += 256) {
            int m = i >> 5, k = i & 31;
            As[k * 68 + m] = A[(size_t)(m0 + m) * Kd + k0 + k];
        }
        for (int i = tid; i < KCH * 64; i += 256) {
            int k = i >> 6, n = i & 63;
            Bs[k * 68 + n] = B[(size_t)(k0 + k) * N + n0 + n];
        }
        __syncthreads();
        #pragma unroll
        for (int k = 0; k < KCH; k++) {
            float4 bv = *(const float4*)&Bs[k * 68 + tx * 4];
            float4 av = *(const float4*)&As[k * 68 + ty * 4];
            acc[0][0] += av.x * bv.x; acc[0][1] += av.x * bv.y; acc[0][2] += av.x * bv.z; acc[0][3] += av.x * bv.w;
            acc[1][0] += av.y * bv.x; acc[1][1] += av.y * bv.y; acc[1][2] += av.y * bv.z; acc[1][3] += av.y * bv.w;
            acc[2][0] += av.z * bv.x; acc[2][1] += av.z * bv.y; acc[2][2] += av.z * bv.z; acc[2][3] += av.z * bv.w;
            acc[3][0] += av.w * bv.x; acc[3][1] += av.w * bv.y; acc[3][2] += av.w * bv.z; acc[3][3] += av.w * bv.w;
        }
        __syncthreads();
    }
    #pragma unroll
    for (int i = 0; i < 4; i++) {
        float4 r = make_float4(acc[i][0], acc[i][1], acc[i][2], acc[i][3]);
        *(float4*)&C[(size_t)(m0 + ty * 4 + i) * N + n0 + tx * 4] = r;
    }
}

// ---------------- LayerNorm + exact GELU ----------------
__global__ void ln_gelu_kernel(const float* __restrict__ X, const float* __restrict__ b1,
                               const float* __restrict__ g, const float* __restrict__ b,
                               float* __restrict__ G)
{
    int row = blockIdx.x, t = threadIdx.x;
    float v = X[(size_t)row * DD + t] + b1[t];
    float mu = blockReduceSum256(v) * (1.0f / DD);
    float d = v - mu;
    float var = blockReduceSum256(d * d) * (1.0f / DD);
    float y = d * rsqrtf(var + EPSF) * g[t] + b[t];
    G[(size_t)row * DD + t] = 0.5f * y * (1.0f + erff(y * 0.7071067811865476f));
}

// ---------------- query projection + fp32 + bf16 split ----------------
__global__ void projq_kernel(const float* __restrict__ X, const float* __restrict__ b2,
                             float* __restrict__ qb,
                             __nv_bfloat16* __restrict__ qhi, __nv_bfloat16* __restrict__ qlo,
                             float* __restrict__ x2o)
{
    int row = blockIdx.x, t = threadIdx.x;
    float v = X[(size_t)row * DD + t] + b2[t];
    float ss = blockReduceSum256(v * v);
    float norm = sqrtf(ss);
    float scale = (norm > MAXN) ? (MAXN / fmaxf(norm, EPSF)) : 1.0f;
    float y = v * scale;
    qb[(size_t)row * DD + t] = y;
    __nv_bfloat16 h = __float2bfloat16(y);
    qhi[(size_t)row * DD + t] = h;
    qlo[(size_t)row * DD + t] = __float2bfloat16(y - __bfloat162float(h));
    float y2 = blockReduceSum256(y * y);
    if (t == 0) x2o[row] = y2;
}

// ---------------- memory bank projection + bf16 split (warp per row) ----------------
__global__ void __launch_bounds__(256) memprep_warp(
    const float* __restrict__ mem, float* __restrict__ mb,
    __nv_bfloat16* __restrict__ mhi, __nv_bfloat16* __restrict__ mlo,
    float* __restrict__ y2o)
{
    int row = blockIdx.x * 8 + (threadIdx.x >> 5);
    int lane = threadIdx.x & 31;
    const float4* xr = (const float4*)(mem + (size_t)row * DD);
    float4 v0 = xr[lane * 2], v1 = xr[lane * 2 + 1];
    float vv[8] = {v0.x, v0.y, v0.z, v0.w, v1.x, v1.y, v1.z, v1.w};
    float s = 0.f;
    #pragma unroll
    for (int i = 0; i < 8; i++) s += vv[i] * vv[i];
    float ss = warpSum(s);
    float norm = sqrtf(ss);
    float scale = (norm > MAXN) ? (MAXN / fmaxf(norm, EPSF)) : 1.0f;
    float y[8];
    float t2 = 0.f;
    #pragma unroll
    for (int i = 0; i < 8; i++) { y[i] = vv[i] * scale; t2 += y[i] * y[i]; }
    float tot = warpSum(t2);
    float4* mo = (float4*)(mb + (size_t)row * DD);
    mo[lane * 2]     = make_float4(y[0], y[1], y[2], y[3]);
    mo[lane * 2 + 1] = make_float4(y[4], y[5], y[6], y[7]);
    uint32_t hp[4], lp[4];
    #pragma unroll
    for (int i = 0; i < 4; i++) {
        float a = y[2 * i], b = y[2 * i + 1];
        float ha = __bfloat162float(__float2bfloat16(a));
        float hb = __bfloat162float(__float2bfloat16(b));
        hp[i] = packbf2(a, b);
        lp[i] = packbf2(a - ha, b - hb);
    }
    *(uint4*)(mhi + (size_t)row * DD + lane * 8) = make_uint4(hp[0], hp[1], hp[2], hp[3]);
    *(uint4*)(mlo + (size_t)row * DD + lane * 8) = make_uint4(lp[0], lp[1], lp[2], lp[3]);
    if (lane == 0) y2o[row] = tot;
}

// ---------------- distance GEMM + top-K (tcgen05 or FFMA fallback) ----------------
__global__ void __launch_bounds__(256, 1) topk_kernel(
    const __nv_bfloat16* __restrict__ qhip, const __nv_bfloat16* __restrict__ qlop,
    const float* __restrict__ qbp, const float* __restrict__ x2p,
    const __nv_bfloat16* __restrict__ mhip, const __nv_bfloat16* __restrict__ mlop,
    const float* __restrict__ mbp, const float* __restrict__ y2p,
    float* __restrict__ pkey, int* __restrict__ pidx)
{
    extern __shared__ char sm[];
    int tid = threadIdx.x;
    int q0 = blockIdx.x * QT;
    int mbase = blockIdx.y * MSL;
    float* lkeyS = (float*)(sm + OFF_LKEY);
    int*   lidxS = (int*)(sm + OFF_LIDX);

#if USE_TC5
    uint32_t smem_base = s2u(sm);
    int lane = tid & 31, wid = tid >> 5;
    uint32_t bar_full0  = smem_base + OFF_BAR;
    uint32_t bar_empty0 = smem_base + OFF_BAR + 16;
    uint32_t bar_drdy0  = smem_base + OFF_BAR + 32;
    uint32_t bar_dfree0 = smem_base + OFF_BAR + 48;
    float* sy2s = (float*)(sm + OFF_Y2);

    if (wid == 0) TCGEN05_ALLOC(smem_base + OFF_TM, 512);
    if (tid == 0) {
        MBARRIER_INIT(bar_full0, 96);      MBARRIER_INIT(bar_full0 + 8, 96);
        MBARRIER_INIT(bar_empty0, 128);    MBARRIER_INIT(bar_empty0 + 8, 128);
        MBARRIER_INIT(bar_drdy0, 1);       MBARRIER_INIT(bar_drdy0 + 8, 1);
        MBARRIER_INIT(bar_dfree0, 4);      MBARRIER_INIT(bar_dfree0 + 8, 4);
    }
    __syncthreads();
    uint32_t tmem_base;
    asm volatile("ld.shared.b32 %0, [%1];" : "=r"(tmem_base) : "r"(smem_base + OFF_TM));

    if (tid < 128) {   // prologue: A (hi+lo) -> TMEM
        uint32_t warp_off = (uint32_t)(tid >> 5) << 21;
        const uint4* qh = (const uint4*)(qhip + (size_t)(q0 + tid) * DD);
        const uint4* ql = (const uint4*)(qlop + (size_t)(q0 + tid) * DD);
        #pragma unroll
        for (int ch = 0; ch < 4; ch++) {
            uint32_t r[32];
            #pragma unroll
            for (int j = 0; j < 8; j++) {
                uint4 v = qh[ch * 8 + j];
                r[j * 4] = v.x; r[j * 4 + 1] = v.y; r[j * 4 + 2] = v.z; r[j * 4 + 3] = v.w;
            }
            TCGEN05_ST_X32(tmem_base + 128 + ch * 32 + warp_off, r);
            #pragma unroll
            for (int j = 0; j < 8; j++) {
                uint4 v = ql[ch * 8 + j];
                r[j * 4] = v.x; r[j * 4 + 1] = v.y; r[j * 4 + 2] = v.z; r[j * 4 + 3] = v.w;
            }
            TCGEN05_ST_X32(tmem_base + 256 + ch * 32 + warp_off, r);
        }
        TCGEN05_WAIT_ST();
        TCGEN05_FENCE_BEFORE();
        #pragma unroll
        for (int j = 0; j < KNN; j++) { lkeyS[tid * KNN + j] = FINF; lidxS[tid * KNN + j] = 0; }
    }
    __syncthreads();

    if (tid < 128) {   // epilogue role
        float x2v = x2p[q0 + tid];
        float omx2v = 1.0f - x2v;
        for (int t = 0; t < TILES; t++) {
            int s = t & 1, u = t >> 1;
            MBARRIER_WAIT_PARITY(bar_drdy0 + s * 8, u & 1);
            TCGEN05_FENCE_AFTER();
            uint32_t dr[64];
            TCGEN05_LD_X32(dr, tmem_base + s * 64);
            TCGEN05_LD_X32(dr + 32, tmem_base + s * 64 + 32);
            TCGEN05_WAIT_LD();
            TCGEN05_FENCE_BEFORE();
            if (lane == 0) MBARRIER_ARRIVE(bar_dfree0 + s * 8);
            float worst = lkeyS[tid * KNN + KNN - 1];
            int midx0 = mbase + t * MT;
            #pragma unroll 4
            for (int c = 0; c < MT; c++) {
                float y2v = sy2s[s * 64 + c];
                float a = __uint_as_float(dr[c]);
                float sq = fmaxf(x2v + y2v - 2.0f * a, 0.0f);
                float den = fmaxf(omx2v * (1.0f - y2v), EPSF);
                float kv = __fdividef(sq, den);
                if (kv < worst) {
                    int pos = KNN - 1;
                    while (pos > 0 && lkeyS[tid * KNN + pos - 1] > kv) {
                        lkeyS[tid * KNN + pos] = lkeyS[tid * KNN + pos - 1];
                        lidxS[tid * KNN + pos] = lidxS[tid * KNN + pos - 1];
                        pos--;
                    }
                    lkeyS[tid * KNN + pos] = kv;
                    lidxS[tid * KNN + pos] = midx0 + c;
                    worst = lkeyS[tid * KNN + KNN - 1];
                }
            }
            MBARRIER_ARRIVE(bar_empty0 + s * 8);
        }
        int obase = ((q0 + tid) * NSLICE + blockIdx.y) * KNN;
        #pragma unroll
        for (int j = 0; j < KNN; j++) {
            pkey[obase + j] = lkeyS[tid * KNN + j];
            pidx[obase + j] = lidxS[tid * KNN + j];
        }
    } else if (wid == 4) {   // MMA issuer role
        TCGEN05_FENCE_AFTER();
        for (int t = 0; t < TILES; t++) {
            int s = t & 1, u = t >> 1;
            MBARRIER_WAIT_PARITY(bar_full0 + s * 8, u & 1);
            MBARRIER_WAIT_PARITY(bar_dfree0 + s * 8, (u & 1) ^ 1);
            TCGEN05_FENCE_AFTER();
            if (elect_one_pred()) {
                uint64_t dhi = MAKE_SMEM_DESC(smem_base + OFF_B + s * BSTAGE);
                uint64_t dlo = MAKE_SMEM_DESC(smem_base + OFF_B + s * BSTAGE + 32768);
                uint32_t dt = tmem_base + s * 64;
                #pragma unroll 1
                for (int st = 0; st < 16; st++) {
                    uint64_t off = (uint64_t)(((st >> 2) << 9) + ((st & 3) << 1));
                    uint32_t ahi = tmem_base + 128 + st * 8;
                    uint32_t alo = tmem_base + 256 + st * 8;
                    TCGEN05_MMA_F16_TS(dt, ahi, dhi + off, IDESC, st > 0 ? 1u : 0u);
                    TCGEN05_MMA_F16_TS(dt, ahi, dlo + off, IDESC, 1u);
                    TCGEN05_MMA_F16_TS(dt, alo, dhi + off, IDESC, 1u);
                }
                TCGEN05_COMMIT(bar_drdy0 + s * 8);
            }
        }
    } else {   // loader role (96 threads)
        int lt = tid - 160;
        for (int t = 0; t < TILES; t++) {
            int s = t & 1, u = t >> 1;
            MBARRIER_WAIT_PARITY(bar_empty0 + s * 8, (u & 1) ^ 1);
            const __nv_bfloat16* gh = mhip + (size_t)(mbase + t * MT) * DD;
            const __nv_bfloat16* gl = mlop + (size_t)(mbase + t * MT) * DD;
            char* bh = sm + OFF_B + s * BSTAGE;
            char* bl = bh + 32768;
            for (int i = lt; i < 2048; i += 96) {
                int r = i >> 5, cc = i & 31;
                uint32_t bo = (uint32_t)(((r >> 3) + (cc >> 3) * 8) * 1024 + (r & 7) * 128 + (cc & 7) * 16);
                uint32_t sw = bo ^ ((bo >> 3) & 0x70);
                *(uint4*)(bh + sw) = *(const uint4*)(gh + (size_t)r * DD + cc * 8);
                *(uint4*)(bl + sw) = *(const uint4*)(gl + (size_t)r * DD + cc * 8);
            }
            if (lt < 64) sy2s[s * 64 + lt] = y2p[mbase + t * MT + lt];
            FENCE_PROXY_ASYNC();
            MBARRIER_ARRIVE(bar_full0 + s * 8);
        }
    }
    __syncthreads();
    if (wid == 0) TCGEN05_DEALLOC(tmem_base, 512);
#else
    // ---------------- FFMA fallback (fp32 exact) ----------------
    float* qsT  = (float*)sm;                    // [32][136] k-major queries
    float* msT  = qsT + 32 * 136;                // [32][68]
    float* keyb = msT + 32 * 68;                 // [128][65]
    float* sx2  = keyb + 128 * 65;               // [128]
    float* sy2  = sx2 + 128;                     // [64]
    int tx = tid & 15, ty = tid >> 4;

    if (tid < 128) {
        sx2[tid] = x2p[q0 + tid];
        #pragma unroll
        for (int j = 0; j < KNN; j++) { lkeyS[tid * KNN + j] = FINF; lidxS[tid * KNN + j] = 0; }
    }

    for (int mt = 0; mt < MSL; mt += MT) {
        float acc[8][4] = {};
        for (int kc = 0; kc < DD; kc += KCH) {
            __syncthreads();
            for (int i = tid; i < QT * KCH; i += 256) {
                int q = i >> 5, k = i & 31;
                qsT[k * 136 + q] = qbp[(size_t)(q0 + q) * DD + kc + k];
            }
            for (int i = tid; i < MT * KCH; i += 256) {
                int m = i >> 5, k = i & 31;
                msT[k * 68 + m] = mbp[(size_t)(mbase + mt + m) * DD + kc + k];
            }
            if (kc == 0 && tid < MT) sy2[tid] = y2p[mbase + mt + tid];
            __syncthreads();
            #pragma unroll
            for (int k = 0; k < KCH; k++) {
                float4 mv = *(const float4*)&msT[k * 68 + tx * 4];
                float4 q0v = *(const float4*)&qsT[k * 136 + ty * 8];
                float4 q1v = *(const float4*)&qsT[k * 136 + ty * 8 + 4];
                float qv[8] = {q0v.x, q0v.y, q0v.z, q0v.w, q1v.x, q1v.y, q1v.z, q1v.w};
                #pragma unroll
                for (int i = 0; i < 8; i++) {
                    acc[i][0] += qv[i] * mv.x; acc[i][1] += qv[i] * mv.y;
                    acc[i][2] += qv[i] * mv.z; acc[i][3] += qv[i] * mv.w;
                }
            }
        }
        #pragma unroll
        for (int i = 0; i < 8; i++) {
            int lq = ty * 8 + i;
            float x2v = sx2[lq], omx2v = 1.0f - x2v;
            #pragma unroll
            for (int j = 0; j < 4; j++) {
                int lm = tx * 4 + j;
                float y2v = sy2[lm];
                float sq = fmaxf(x2v + y2v - 2.0f * acc[i][j], 0.0f);
                float den = fmaxf(omx2v * (1.0f - y2v), EPSF);
                keyb[lq * 65 + lm] = sq / den;
            }
        }
        __syncthreads();
        if (tid < 128) {
            float worst = lkeyS[tid * KNN + KNN - 1];
            int midx0 = mbase + mt;
            for (int m = 0; m < MT; m++) {
                float kv = keyb[tid * 65 + m];
                if (kv < worst) {
                    int pos = KNN - 1;
                    while (pos > 0 && lkeyS[tid * KNN + pos - 1] > kv) {
                        lkeyS[tid * KNN + pos] = lkeyS[tid * KNN + pos - 1];
                        lidxS[tid * KNN + pos] = lidxS[tid * KNN + pos - 1];
                        pos--;
                    }
                    lkeyS[tid * KNN + pos] = kv;
                    lidxS[tid * KNN + pos] = midx0 + m;
                    worst = lkeyS[tid * KNN + KNN - 1];
                }
            }
        }
    }
    __syncthreads();
    if (tid < 128) {
        int obase = ((q0 + tid) * NSLICE + blockIdx.y) * KNN;
        #pragma unroll
        for (int j = 0; j < KNN; j++) {
            pkey[obase + j] = lkeyS[tid * KNN + j];
            pidx[obase + j] = lidxS[tid * KNN + j];
        }
    }
#endif
}

// ---------------- merge partial top-K, arccosh, softmax, gather ----------------
__global__ void merge_kernel(const float* __restrict__ pkey, const int* __restrict__ pidx,
                             const float* __restrict__ mb, float* __restrict__ ret)
{
    int q = blockIdx.x, t = threadIdx.x;   // 128 threads
    __shared__ float skey[CAND];
    __shared__ int   sidx[CAND];
    __shared__ float wkey[KNN];
    __shared__ int   widx[KNN];
    __shared__ float wgt[KNN];

    float myk = pkey[(size_t)q * CAND + t];
    int   myi = pidx[(size_t)q * CAND + t];

    for (int j = 0; j < KNN; j++) {
        skey[t] = myk; sidx[t] = myi;
        __syncthreads();
        for (int s = CAND / 2; s > 0; s >>= 1) {
            if (t < s) {
                float k2 = skey[t + s]; int i2 = sidx[t + s];
                if (k2 < skey[t] || (k2 == skey[t] && i2 < sidx[t])) { skey[t] = k2; sidx[t] = i2; }
            }
            __syncthreads();
        }
        if (t == 0) { wkey[j] = skey[0]; widx[j] = sidx[0]; }
        __syncthreads();
        if (myi == widx[j]) myk = FINF;
    }

    if (t == 0) {
        float dv[KNN];
        #pragma unroll
        for (int j = 0; j < KNN; j++) {
            float arg = fmaxf(1.0f + 2.0f * wkey[j], 1.0f + EPSF);
            dv[j] = logf(arg + sqrtf(arg * arg - 1.0f));
        }
        float dmin = dv[0];
        #pragma unroll
        for (int j = 1; j < KNN; j++) dmin = fminf(dmin, dv[j]);
        float s = 0.0f;
        #pragma unroll
        for (int j = 0; j < KNN; j++) { float e = expf(dmin - dv[j]); wgt[j] = e; s += e; }
        float inv = 1.0f / s;
        #pragma unroll
        for (int j = 0; j < KNN; j++) wgt[j] *= inv;
    }
    __syncthreads();

    for (int c = t; c < DD; c += 128) {
        float acc = 0.0f;
        #pragma unroll
        for (int j = 0; j < KNN; j++) acc += wgt[j] * mb[(size_t)widx[j] * DD + c];
        ret[(size_t)q * DD + c] = acc;
    }
}

// ---------------- residual epilogue ----------------
__global__ void final_kernel(const float* __restrict__ hidden, const float* __restrict__ go,
                             const float* __restrict__ bp, float* __restrict__ out)
{
    int i = blockIdx.x * 256 + threadIdx.x;
    out[i] = hidden[i] + 0.1f * (go[i] + bp[i & (HID - 1)]);
}

// ---------------- launcher ----------------
extern "C" void kernel_launch(void* const* d_in, const int* in_sizes, int n_in,
                              void* d_out, int out_size)
{
    const float* hidden = (const float*)d_in[0];
    const float* memory = (const float*)d_in[1];
    const float* w1     = (const float*)d_in[2];
    const float* b1     = (const float*)d_in[3];
    const float* ln_g   = (const float*)d_in[4];
    const float* ln_b   = (const float*)d_in[5];
    const float* w2     = (const float*)d_in[6];
    const float* b2     = (const float*)d_in[7];
    const float* wp     = (const float*)d_in[8];
    const float* bp     = (const float*)d_in[9];
    float* out = (float*)d_out;

    float *tmp1, *G, *tmp2, *qb, *x2, *mb, *y2, *pkey, *ret, *tmp3;
    __nv_bfloat16 *qhi, *qlo, *mhi, *mlo;
    int* pidx;
    cudaGetSymbolAddress((void**)&tmp1, g_tmp1);
    cudaGetSymbolAddress((void**)&G,    g_G);
    cudaGetSymbolAddress((void**)&tmp2, g_tmp2);
    cudaGetSymbolAddress((void**)&qb,   g_qb);
    cudaGetSymbolAddress((void**)&qhi,  g_qhi);
    cudaGetSymbolAddress((void**)&qlo,  g_qlo);
    cudaGetSymbolAddress((void**)&x2,   g_x2);
    cudaGetSymbolAddress((void**)&mb,   g_mb);
    cudaGetSymbolAddress((void**)&mhi,  g_mhi);
    cudaGetSymbolAddress((void**)&mlo,  g_mlo);
    cudaGetSymbolAddress((void**)&y2,   g_y2);
    cudaGetSymbolAddress((void**)&pkey, g_pkey);
    cudaGetSymbolAddress((void**)&pidx, g_pidx);
    cudaGetSymbolAddress((void**)&ret,  g_ret);
    cudaGetSymbolAddress((void**)&tmp3, g_tmp3);

    cudaFuncSetAttribute(topk_kernel, cudaFuncAttributeMaxDynamicSharedMemorySize, SMEMB);

    gemm64x64<<<dim3(NQ / 64, DD / 64), 256>>>(hidden, w1, tmp1, NQ, DD, HID);
    ln_gelu_kernel<<<NQ, 256>>>(tmp1, b1, ln_g, ln_b, G);
    gemm64x64<<<dim3(NQ / 64, DD / 64), 256>>>(G, w2, tmp2, NQ, DD, DD);
    projq_kernel<<<NQ, 256>>>(tmp2, b2, qb, qhi, qlo, x2);

    memprep_warp<<<MM / 8, 256>>>(memory, mb, mhi, mlo, y2);

    topk_kernel<<<dim3(NQ / QT, NSLICE), 256, SMEMB>>>(qhi, qlo, qb, x2, mhi, mlo, mb, y2, pkey, pidx);

    merge_kernel<<<NQ, 128>>>(pkey, pidx, mb, ret);

    gemm64x64<<<dim3(NQ / 64, HID / 64), 256>>>(ret, wp, tmp3, NQ, HID, DD);
    final_kernel<<<NQ * HID / 256, 256>>>(hidden, tmp3, bp, out);
}